// round 11
// baseline (speedup 1.0000x reference)
#include <cuda_runtime.h>

// x: [8, 64, 64, 64, 64] fp32. Per (b,c) slice of 64^3:
//   s = sum over 2x2x2 windows of (max(window) + mean(window))
//   pooled[b,c] = s^2 ;  out[b,c] = pooled / max(||pooled[b,:]||_2, 1e-12)
//
// Dynamic work-stealing: 1036 blocks (148 SMs x 7, one wave) x 128 threads
// pull 128 KB units (4096 = 512 slices x 8 h2-chunks) from a global atomic
// counter. Absorbs both round-count imbalance and inter-SM L2-die/queue
// spread. Each unit writes a DETERMINISTIC slot g_partial[u] (steal order
// cannot affect values). Fused last-block finalize via done-ticket.

#define NBC   512
#define NUNIT 4096              // 512 slices x 8 chunks (4 h2 rows each)
#define NBLK  1036              // 148 * 7

__device__ float g_partial[NUNIT];
__device__ unsigned int g_next = 0;
__device__ unsigned int g_done = 0;

__global__ __launch_bounds__(128, 7) void fused_pool_kernel(const float* __restrict__ x,
                                                            float* __restrict__ out) {
    const int tid = threadIdx.x;       // 128 threads
    const int tx  = tid & 15;          // d-group: d = 4*tx..4*tx+3 (two d2 windows)
    const int g   = tid >> 4;          // 0..7: w2 start; strided by 8

    __shared__ unsigned int s_u;
    __shared__ float swarp[4];
    __shared__ int s_islast;

    for (;;) {
        if (tid == 0) s_u = atomicAdd(&g_next, 1u);
        __syncthreads();
        const unsigned int u = s_u;
        __syncthreads();               // protect s_u before next leader write
        if (u >= NUNIT) break;

        const int bc = u >> 3;
        const int q  = u & 7;          // h2 in [q*4, q*4+4)
        const float* r0 = x + (size_t)bc * (64 * 64 * 64)
                            + ((size_t)(q * 8) * 4096) + (2 * g * 64) + (tx << 2);

        float acc = 0.0f;
        #pragma unroll
        for (int h2i = 0; h2i < 4; h2i++) {       // 4 h2 rows in this unit
            const float* r = r0;
            #pragma unroll
            for (int w2i = 0; w2i < 4; w2i++) {   // w2 = g + 8*w2i
                const float4 a = *(const float4*)(r);                 // (2h2,   2w2  )
                const float4 b = *(const float4*)(r + 64);            // (2h2,   2w2+1)
                const float4 c = *(const float4*)(r + 4096);          // (2h2+1, 2w2  )
                const float4 d = *(const float4*)(r + 4096 + 64);     // (2h2+1, 2w2+1)

                float m0 = fmaxf(fmaxf(fmaxf(a.x, a.y), fmaxf(b.x, b.y)),
                                 fmaxf(fmaxf(c.x, c.y), fmaxf(d.x, d.y)));
                float m1 = fmaxf(fmaxf(fmaxf(a.z, a.w), fmaxf(b.z, b.w)),
                                 fmaxf(fmaxf(c.z, c.w), fmaxf(d.z, d.w)));

                float sum = (a.x + a.y + a.z + a.w) + (b.x + b.y + b.z + b.w)
                          + (c.x + c.y + c.z + c.w) + (d.x + d.y + d.z + d.w);

                acc += m0 + m1 + sum * 0.125f;
                r += 2 * 8 * 64;                  // w2 += 8
            }
            r0 += 2 * 4096;                       // h2 += 1
        }

        // block reduce -> deterministic slot
        #pragma unroll
        for (int off = 16; off > 0; off >>= 1)
            acc += __shfl_xor_sync(0xFFFFFFFFu, acc, off);
        if ((tid & 31) == 0) swarp[tid >> 5] = acc;
        __syncthreads();
        if (tid == 0)
            g_partial[u] = swarp[0] + swarp[1] + swarp[2] + swarp[3];
        // (swarp rewritten only after next unit's loads + shuffle; the
        //  __syncthreads at loop top orders it)
    }

    if (tid == 0) {
        __threadfence();               // publish partials before ticket
        unsigned int old = atomicAdd(&g_done, 1u);
        s_islast = (old == (unsigned int)(gridDim.x - 1));
    }
    __syncthreads();
    if (!s_islast) return;

    // ---- last block: finalize (all 4096 partials visible) ----
    __threadfence();
    __shared__ float s_norm[8];

    const int b  = tid >> 4;           // 0..7
    const int c4 = (tid & 15) << 2;    // 0,4,...,60

    float p[4], qsum = 0.0f;
    #pragma unroll
    for (int k = 0; k < 4; k++) {
        const int idx = ((b << 6) + c4 + k) << 3;  // 8 partials per channel
        float s = 0.0f;
        #pragma unroll
        for (int j = 0; j < 8; j++) s += g_partial[idx + j];
        p[k] = s * s;
        qsum += p[k] * p[k];
    }

    #pragma unroll
    for (int off = 8; off > 0; off >>= 1)
        qsum += __shfl_xor_sync(0xFFFFFFFFu, qsum, off);

    if ((tid & 15) == 0) s_norm[b] = fmaxf(sqrtf(qsum), 1e-12f);
    __syncthreads();

    const float inv = 1.0f / s_norm[b];
    #pragma unroll
    for (int k = 0; k < 4; k++)
        out[(b << 6) + c4 + k] = p[k] * inv;

    if (tid == 0) { g_next = 0; g_done = 0; }   // reset for next graph replay
}

extern "C" void kernel_launch(void* const* d_in, const int* in_sizes, int n_in,
                              void* d_out, int out_size) {
    const float* x = (const float*)d_in[0];
    float* out = (float*)d_out;
    fused_pool_kernel<<<NBLK, 128>>>(x, out);
}